// round 1
// baseline (speedup 1.0000x reference)
#include <cuda_runtime.h>

// Problem constants
#define P_SZ   16
#define IMG    224
#define NP     14
#define TOTAL  196           // 14*14 patches
#define DDIM   768           // 16*16*3
#define B_TOT  256
#define IMGSZ  150528        // 3*224*224
#define CH_SZ  50176         // 224*224
#define SLAB   9408          // weights per ph slab: 16*588
#define NB     8             // batches per block
#define NBG    (B_TOT / NB)  // 32 batch groups
#define NWARPS 8
#define NITERS 294           // c(3) * i(14) * j0(7)

// Partial sums: [ph][b][t]  (3.2 MB device scratch, allowed as __device__ global)
__device__ float g_scratch[16 * B_TOT * TOTAL];

__global__ __launch_bounds__(256)
void patch_score_main(const float* __restrict__ x,
                      const float* __restrict__ w) {
    __shared__ float w_s[SLAB];            // 37632 B
    __shared__ float acc_s[TOTAL * NB];    // 6272 B

    const int ph = blockIdx.x & 15;
    const int bg = blockIdx.x >> 4;
    const int tid = threadIdx.x;

    // zero block accumulator
    for (int k = tid; k < TOTAL * NB; k += 256) acc_s[k] = 0.0f;
    // stage this ph's contiguous weight slab [9408*ph, 9408*(ph+1))
    const float* wslab = w + ph * SLAB;
    for (int k = tid; k < SLAB; k += 256) w_s[k] = wslab[k];
    __syncthreads();

    const int warp = tid >> 5;
    const int lane = tid & 31;
    const int pw   = lane & 15;
    const int joff = lane >> 4;

    // Per-lane: F = fbase + g, g in [0,588) -> at most 2 patch bins
    const int fbase = ph * SLAB + pw * 588;
    const int tA    = fbase / 768;
    const int gstar = 768 * (tA + 1) - fbase;   // in [1,768]

    float accA[NB], accB[NB];
    #pragma unroll
    for (int b = 0; b < NB; b++) { accA[b] = 0.0f; accB[b] = 0.0f; }

    const int b0 = bg * NB;
    const float* xg = x + (size_t)b0 * IMGSZ;

    // iterate (c, i, j0) combos, strided across warps
    for (int it = warp; it < NITERS; it += NWARPS) {
        const int c  = it / 98;
        const int r  = it - c * 98;
        const int i  = r / 7;
        const int j0 = (r - i * 7) * 2;

        const int g = 196 * c + 14 * i + j0 + joff;
        const float wv = w_s[pw * 588 + g];
        const float* xp = xg + c * CH_SZ + (16 * i + ph) * IMG + 16 * j0 + lane;
        const bool pA = (g < gstar);

        #pragma unroll
        for (int b = 0; b < NB; b++) {
            const float xv = xp[b * IMGSZ];       // coalesced 128B warp load
            if (pA) accA[b] = fmaf(xv, wv, accA[b]);
            else    accB[b] = fmaf(xv, wv, accB[b]);
        }
    }

    // flush per-lane bins into block accumulator (once per warp)
    #pragma unroll
    for (int b = 0; b < NB; b++) atomicAdd(&acc_s[tA * NB + b], accA[b]);
    if (gstar < 588) {  // bin B can only exist if threshold inside g-range
        #pragma unroll
        for (int b = 0; b < NB; b++) atomicAdd(&acc_s[(tA + 1) * NB + b], accB[b]);
    }
    __syncthreads();

    // deterministic partial write: scratch[ph][b0+b][t]
    float* sc = g_scratch + ph * (B_TOT * TOTAL);
    for (int k = tid; k < TOTAL * NB; k += 256) {
        const int t = k / NB;
        const int b = k & (NB - 1);
        sc[(b0 + b) * TOTAL + t] = acc_s[k];
    }
}

__global__ void patch_score_reduce(const float* __restrict__ bias,
                                   float* __restrict__ out) {
    const int idx = blockIdx.x * blockDim.x + threadIdx.x;  // over B_TOT*TOTAL
    if (idx >= B_TOT * TOTAL) return;
    const int t = idx % TOTAL;
    float s = bias[t];
    #pragma unroll
    for (int ph = 0; ph < 16; ph++)
        s += g_scratch[ph * (B_TOT * TOTAL) + idx];
    out[idx] = s;
}

extern "C" void kernel_launch(void* const* d_in, const int* in_sizes, int n_in,
                              void* d_out, int out_size) {
    const float* x    = (const float*)d_in[0];   // [256,3,224,224]
    const float* wgt  = (const float*)d_in[1];   // [196,768]
    const float* bias = (const float*)d_in[2];   // [196]
    float* out = (float*)d_out;                  // [256,196]

    patch_score_main<<<16 * NBG, 256>>>(x, wgt);
    patch_score_reduce<<<(B_TOT * TOTAL + 255) / 256, 256>>>(bias, out);
}